// round 5
// baseline (speedup 1.0000x reference)
#include <cuda_runtime.h>
#include <math.h>

// Problem constants
#define BB 64
#define WW 16
#define CC 64
#define TT 1024
#define DE 64
#define NBW 1024           // B*W
#define NROWS 65536        // B*W*C
#define XR_ELEMS 67108864  // B*C*W*T

// -------- device scratch (no allocations allowed) --------
__device__ float g_stat[NROWS];   // [bw][c]
__device__ float g_Z[CC * DE];    // [c][d]
__device__ float g_A2[CC * CC];   // A_final @ A_final

// -------- f32x2 helpers --------
__device__ __forceinline__ unsigned long long pack2(float a, float b) {
    unsigned long long r;
    asm("mov.b64 %0, {%1, %2};" : "=l"(r) : "f"(a), "f"(b));
    return r;
}
__device__ __forceinline__ unsigned long long ffma2(unsigned long long a,
                                                    unsigned long long b,
                                                    unsigned long long c) {
    unsigned long long d;
    asm("fma.rn.f32x2 %0, %1, %2, %3;" : "=l"(d) : "l"(a), "l"(b), "l"(c));
    return d;
}
__device__ __forceinline__ void unpack2(unsigned long long v, float& a, float& b) {
    asm("mov.b64 {%0, %1}, %2;" : "=f"(a), "=f"(b) : "l"(v));
}

// ================= Kernel 1: per-row stats =================
// stat[r] = 0.5 * (mean + energy) over T, r = ((b*W+w)*C + c)
__global__ void k_stats(const float* __restrict__ x) {
    int warp = (blockIdx.x * blockDim.x + threadIdx.x) >> 5;
    int lane = threadIdx.x & 31;
    if (warp >= NROWS) return;
    const float4* p = reinterpret_cast<const float4*>(x) + (size_t)warp * 256;
    float s1 = 0.f, s2 = 0.f;
#pragma unroll
    for (int k = 0; k < 8; k++) {
        float4 v = p[lane + 32 * k];
        s1 += (v.x + v.y) + (v.z + v.w);
        s2 += v.x * v.x + v.y * v.y + v.z * v.z + v.w * v.w;
    }
#pragma unroll
    for (int off = 16; off > 0; off >>= 1) {
        s1 += __shfl_xor_sync(0xffffffffu, s1, off);
        s2 += __shfl_xor_sync(0xffffffffu, s2, off);
    }
    if (lane == 0) g_stat[warp] = 0.5f * (s1 + s2) * (1.0f / 1024.0f);
}

// ================= Kernel 2: Z_mean[c][d] =================
__global__ void k_zmean(const float* __restrict__ Wp) {
    __shared__ float scol[NBW];
    __shared__ float swp[DE];
    __shared__ float part[256];
    int c = blockIdx.x;
    int tid = threadIdx.x;
    if (tid < DE) swp[tid] = Wp[tid];
    for (int i = tid; i < NBW; i += 256) scol[i] = g_stat[i * CC + c];
    __syncthreads();
    int d = tid & 63, grp = tid >> 6;
    float w = swp[d];
    float s = 0.f;
    for (int bw = grp; bw < NBW; bw += 4) s += tanhf(scol[bw] * w);
    part[tid] = s;
    __syncthreads();
    if (tid < 64) {
        float z = (part[tid] + part[tid + 64] + part[tid + 128] + part[tid + 192]) *
                  (1.0f / 1024.0f);
        g_Z[c * DE + tid] = z;
    }
}

// ================= Kernel 3: graph build (single block, 256 thr) =================
__device__ __forceinline__ unsigned rotl32(unsigned v, int s) {
    return (v << s) | (v >> (32 - s));
}
__device__ __forceinline__ void threefry_0_42(unsigned c0, unsigned c1,
                                              unsigned& o0, unsigned& o1) {
    const unsigned ks0 = 0u, ks1 = 42u, ks2 = 0u ^ 42u ^ 0x1BD11BDAu;
    unsigned x0 = c0 + ks0, x1 = c1 + ks1;
#define TF_RND(r) { x0 += x1; x1 = rotl32(x1, r); x1 ^= x0; }
    TF_RND(13) TF_RND(15) TF_RND(26) TF_RND(6)  x0 += ks1; x1 += ks2 + 1u;
    TF_RND(17) TF_RND(29) TF_RND(16) TF_RND(24) x0 += ks2; x1 += ks0 + 2u;
    TF_RND(13) TF_RND(15) TF_RND(26) TF_RND(6)  x0 += ks0; x1 += ks1 + 3u;
    TF_RND(17) TF_RND(29) TF_RND(16) TF_RND(24) x0 += ks1; x1 += ks2 + 4u;
    TF_RND(13) TF_RND(15) TF_RND(26) TF_RND(6)  x0 += ks2; x1 += ks0 + 5u;
#undef TF_RND
    o0 = x0; o1 = x1;
}
// Partitionable threefry (JAX >= 0.4.30 default): counter (hi,lo) = (0, idx),
// 32-bit sample = XOR-fold of the two threefry2x32 output words.
__device__ __forceinline__ float gumbel_at(int idx) {
    unsigned o0, o1;
    threefry_0_42(0u, (unsigned)idx, o0, o1);
    unsigned bits = o0 ^ o1;
    float u = __uint_as_float((bits >> 9) | 0x3f800000u) - 1.0f;
    const float tiny = 1.17549435e-38f;
    float r = fmaxf(tiny, u + tiny);  // u*(1-tiny)+tiny with (1-tiny)==1 in fp32
    return -logf(-logf(r));
}
__device__ __forceinline__ float gelu_exact(float v) {
    return 0.5f * v * (1.0f + erff(v * 0.70710678118654752f));
}
__device__ __forceinline__ float softplus_f(float v) {
    return fmaxf(v, 0.f) + log1pf(expf(-fabsf(v)));
}

__global__ void k_graph(const float* __restrict__ w1, const float* __restrict__ b1,
                        const float* __restrict__ w2, const float* __restrict__ b2,
                        const float* __restrict__ pbeta, const float* __restrict__ pgamma,
                        const float* __restrict__ ptemp, float* __restrict__ outA) {
    __shared__ float sA[4096];
    __shared__ float sS[4096];  // Z, later y scores
    __shared__ float ssq[64];
    __shared__ float sdinv[64];
    __shared__ unsigned long long smask[64];
    __shared__ float sw1[16], sb1[16], sw2[16];
    int tid = threadIdx.x;
    if (tid < 16) { sw1[tid] = w1[tid]; sb1[tid] = b1[tid]; sw2[tid] = w2[tid]; }
    float beta = *pbeta, gamma = *pgamma, b2v = *b2;
    float invt = 1.0f / fmaxf(*ptemp, 1e-6f);

#pragma unroll
    for (int k = 0; k < 16; k++) sS[tid + 256 * k] = g_Z[tid + 256 * k];
    __syncthreads();
    if (tid < 64) {
        float s = 0.f;
#pragma unroll
        for (int m = 0; m < 64; m++) { float z = sS[tid * 64 + m]; s += z * z; }
        ssq[tid] = s;
    }
    __syncthreads();

    // D2 held in registers (16 elements/thread)
    float d2r[16];
#pragma unroll
    for (int k = 0; k < 16; k++) {
        int e = tid + 256 * k, i = e >> 6, j = e & 63;
        float dot = 0.f;
        for (int m = 0; m < 64; m++) dot += sS[i * 64 + m] * sS[j * 64 + m];
        float v = ssq[i] + ssq[j] - 2.0f * dot;
        d2r[k] = fmaxf(v, 0.f) * 0.5f;
        sA[e] = (i == j) ? 1.f : 0.f;
    }
    __syncthreads();

    for (int step = 0; step < 2; step++) {
#pragma unroll
        for (int k = 0; k < 16; k++) {
            int e = tid + 256 * k;
            float a = sA[e] - 0.2f * d2r[k];
            float s = b2v;
#pragma unroll
            for (int m = 0; m < 16; m++) {
                float h = gelu_exact(fmaf(a, sw1[m], sb1[m]));
                s = fmaf(h, sw2[m], s);
            }
            a = a + beta * (softplus_f(s) * gamma);
            sA[e] = a;
        }
        __syncthreads();
        float r1[16], r2[16];
#pragma unroll
        for (int k = 0; k < 16; k++) {
            int e = tid + 256 * k, i = e >> 6, j = e & 63;
            r1[k] = sA[e]; r2[k] = sA[j * 64 + i];
        }
        __syncthreads();
#pragma unroll
        for (int k = 0; k < 16; k++) {
            int e = tid + 256 * k, i = e >> 6, j = e & 63;
            float v = 0.5f * (r1[k] + r2[k]);
            sA[e] = fmaxf(v, 0.f) + ((i == j) ? 1.f : 0.f);
        }
        __syncthreads();
    }

    // Gumbel scores
#pragma unroll
    for (int k = 0; k < 16; k++) {
        int e = tid + 256 * k;
        sS[e] = (sA[e] + gumbel_at(e)) * invt;
    }
    __syncthreads();
    // top-16 per row (tie-break: lowest index via strict >)
    if (tid < 64) {
        float* row = sS + tid * 64;
        unsigned long long m = 0ull;
        for (int p = 0; p < 16; p++) {
            float best = -__int_as_float(0x7f800000);  // -inf
            int bi = 0;
            for (int j = 0; j < 64; j++) {
                float v = row[j];
                if (v > best) { best = v; bi = j; }
            }
            row[bi] = __int_as_float(0xff800000);  // -inf
            m |= (1ull << bi);
        }
        smask[tid] = m;
    }
    __syncthreads();
#pragma unroll
    for (int k = 0; k < 16; k++) {
        int e = tid + 256 * k, i = e >> 6, j = e & 63;
        if (!((smask[i] >> j) & 1ull)) sA[e] = 0.f;
    }
    __syncthreads();
    // symmetrize + relu + I
    {
        float r1[16], r2[16];
#pragma unroll
        for (int k = 0; k < 16; k++) {
            int e = tid + 256 * k, i = e >> 6, j = e & 63;
            r1[k] = sA[e]; r2[k] = sA[j * 64 + i];
        }
        __syncthreads();
#pragma unroll
        for (int k = 0; k < 16; k++) {
            int e = tid + 256 * k, i = e >> 6, j = e & 63;
            float v = fmaxf(0.5f * (r1[k] + r2[k]), 0.f) + ((i == j) ? 1.f : 0.f);
            sA[e] = v;
        }
        __syncthreads();
    }
    // degree normalize
    if (tid < 64) {
        float s = 0.f;
        for (int j = 0; j < 64; j++) s += sA[tid * 64 + j];
        sdinv[tid] = rsqrtf(fmaxf(s, 1e-6f));
    }
    __syncthreads();
#pragma unroll
    for (int k = 0; k < 16; k++) {
        int e = tid + 256 * k, i = e >> 6, j = e & 63;
        float v = sdinv[i] * sA[e] * sdinv[j] + ((i == j) ? 1.f : 0.f);
        sA[e] = v;
        outA[e] = v;  // final A output
    }
    __syncthreads();
    // A2 = A @ A (fuses the two propagation steps)
#pragma unroll
    for (int k = 0; k < 16; k++) {
        int e = tid + 256 * k, i = e >> 6, j = e & 63;
        float s = 0.f;
        for (int m = 0; m < 64; m++) s += sA[i * 64 + m] * sA[m * 64 + j];
        g_A2[e] = s;
    }
}

// ================= Kernel 4: out = A2 @ x (per b,w tile), f32x2 =================
__global__ void __launch_bounds__(256) k_prop(const float* __restrict__ x,
                                              float* __restrict__ out) {
    __shared__ __align__(16) unsigned long long sA2p[64 * 32];  // [j][c2] = (A2[2c2][j], A2[2c2+1][j])
    int tid = threadIdx.x;
#pragma unroll
    for (int k = 0; k < 8; k++) {
        int idx = tid + 256 * k;  // 0..2047
        int j = idx >> 5, c2 = idx & 31;
        float a0 = g_A2[(2 * c2) * 64 + j];
        float a1 = g_A2[(2 * c2 + 1) * 64 + j];
        sA2p[idx] = pack2(a0, a1);
    }
    __syncthreads();

    int bw = blockIdx.x >> 2;
    int t = ((blockIdx.x & 3) << 8) + tid;
    int b = bw >> 4, w = bw & 15;
    const float* xp = x + ((size_t)bw << 16) + t;

    unsigned long long acc[32];
#pragma unroll
    for (int q = 0; q < 32; q++) acc[q] = 0ull;

#pragma unroll 8
    for (int j = 0; j < 64; j++) {
        float xv = xp[(size_t)j << 10];
        unsigned long long xd = pack2(xv, xv);
        const ulonglong2* ap = reinterpret_cast<const ulonglong2*>(sA2p + j * 32);
#pragma unroll
        for (int q = 0; q < 16; q++) {
            ulonglong2 a = ap[q];
            acc[2 * q]     = ffma2(a.x, xd, acc[2 * q]);
            acc[2 * q + 1] = ffma2(a.y, xd, acc[2 * q + 1]);
        }
    }

    float* op = out + (size_t)b * 1048576 + (size_t)w * 1024 + t;
#pragma unroll
    for (int q = 0; q < 32; q++) {
        float lo, hi;
        unpack2(acc[q], lo, hi);
        op[(size_t)(2 * q) * 16384] = lo;
        op[(size_t)(2 * q + 1) * 16384] = hi;
    }
}

// ================= launch =================
extern "C" void kernel_launch(void* const* d_in, const int* in_sizes, int n_in,
                              void* d_out, int out_size) {
    const float* x     = (const float*)d_in[0];
    const float* Wp    = (const float*)d_in[1];
    const float* w1    = (const float*)d_in[2];
    const float* b1    = (const float*)d_in[3];
    const float* w2    = (const float*)d_in[4];
    const float* b2    = (const float*)d_in[5];
    const float* beta  = (const float*)d_in[6];
    const float* gamma = (const float*)d_in[7];
    const float* temp  = (const float*)d_in[8];
    float* out = (float*)d_out;

    k_stats<<<8192, 256>>>(x);
    k_zmean<<<64, 256>>>(Wp);
    k_graph<<<1, 256>>>(w1, b1, w2, b2, beta, gamma, temp, out + XR_ELEMS);
    k_prop<<<4096, 256>>>(x, out);
}

// round 6
// speedup vs baseline: 1.4374x; 1.4374x over previous
#include <cuda_runtime.h>
#include <math.h>

// Problem constants
#define BB 64
#define WW 16
#define CC 64
#define TT 1024
#define DE 64
#define NBW 1024           // B*W
#define NROWS 65536        // B*W*C
#define XR_ELEMS 67108864  // B*C*W*T

// -------- device scratch (no allocations allowed) --------
__device__ float g_stat[NROWS];   // [bw][c]
__device__ float g_Z[CC * DE];    // [c][d]
__device__ float g_A2[CC * CC];   // A_final @ A_final

// -------- f32x2 helpers --------
__device__ __forceinline__ unsigned long long pack2(float a, float b) {
    unsigned long long r;
    asm("mov.b64 %0, {%1, %2};" : "=l"(r) : "f"(a), "f"(b));
    return r;
}
__device__ __forceinline__ unsigned long long ffma2(unsigned long long a,
                                                    unsigned long long b,
                                                    unsigned long long c) {
    unsigned long long d;
    asm("fma.rn.f32x2 %0, %1, %2, %3;" : "=l"(d) : "l"(a), "l"(b), "l"(c));
    return d;
}
__device__ __forceinline__ void unpack2(unsigned long long v, float& a, float& b) {
    asm("mov.b64 {%0, %1}, %2;" : "=f"(a), "=f"(b) : "l"(v));
}

// ================= Kernel 1: per-row stats =================
__global__ void k_stats(const float* __restrict__ x) {
    int warp = (blockIdx.x * blockDim.x + threadIdx.x) >> 5;
    int lane = threadIdx.x & 31;
    if (warp >= NROWS) return;
    const float4* p = reinterpret_cast<const float4*>(x) + (size_t)warp * 256;
    float s1 = 0.f, s2 = 0.f;
#pragma unroll
    for (int k = 0; k < 8; k++) {
        float4 v = p[lane + 32 * k];
        s1 += (v.x + v.y) + (v.z + v.w);
        s2 += v.x * v.x + v.y * v.y + v.z * v.z + v.w * v.w;
    }
#pragma unroll
    for (int off = 16; off > 0; off >>= 1) {
        s1 += __shfl_xor_sync(0xffffffffu, s1, off);
        s2 += __shfl_xor_sync(0xffffffffu, s2, off);
    }
    if (lane == 0) g_stat[warp] = 0.5f * (s1 + s2) * (1.0f / 1024.0f);
}

// ================= Kernel 2: Z_mean[c][d] =================
__global__ void k_zmean(const float* __restrict__ Wp) {
    __shared__ float scol[NBW];
    __shared__ float swp[DE];
    __shared__ float part[256];
    int c = blockIdx.x;
    int tid = threadIdx.x;
    if (tid < DE) swp[tid] = Wp[tid];
    for (int i = tid; i < NBW; i += 256) scol[i] = g_stat[i * CC + c];
    __syncthreads();
    int d = tid & 63, grp = tid >> 6;
    float w = swp[d];
    float s = 0.f;
    for (int bw = grp; bw < NBW; bw += 4) s += tanhf(scol[bw] * w);
    part[tid] = s;
    __syncthreads();
    if (tid < 64) {
        float z = (part[tid] + part[tid + 64] + part[tid + 128] + part[tid + 192]) *
                  (1.0f / 1024.0f);
        g_Z[c * DE + tid] = z;
    }
}

// ================= Kernel 3: graph build (single block, 256 thr) =================
__device__ __forceinline__ unsigned rotl32(unsigned v, int s) {
    return (v << s) | (v >> (32 - s));
}
__device__ __forceinline__ void threefry_0_42(unsigned c0, unsigned c1,
                                              unsigned& o0, unsigned& o1) {
    const unsigned ks0 = 0u, ks1 = 42u, ks2 = 0u ^ 42u ^ 0x1BD11BDAu;
    unsigned x0 = c0 + ks0, x1 = c1 + ks1;
#define TF_RND(r) { x0 += x1; x1 = rotl32(x1, r); x1 ^= x0; }
    TF_RND(13) TF_RND(15) TF_RND(26) TF_RND(6)  x0 += ks1; x1 += ks2 + 1u;
    TF_RND(17) TF_RND(29) TF_RND(16) TF_RND(24) x0 += ks2; x1 += ks0 + 2u;
    TF_RND(13) TF_RND(15) TF_RND(26) TF_RND(6)  x0 += ks0; x1 += ks1 + 3u;
    TF_RND(17) TF_RND(29) TF_RND(16) TF_RND(24) x0 += ks1; x1 += ks2 + 4u;
    TF_RND(13) TF_RND(15) TF_RND(26) TF_RND(6)  x0 += ks2; x1 += ks0 + 5u;
#undef TF_RND
    o0 = x0; o1 = x1;
}
// Partitionable threefry (JAX >= 0.4.30 default): counter (hi,lo) = (0, idx),
// 32-bit sample = XOR-fold of the two threefry2x32 output words.
__device__ __forceinline__ float gumbel_at(int idx) {
    unsigned o0, o1;
    threefry_0_42(0u, (unsigned)idx, o0, o1);
    unsigned bits = o0 ^ o1;
    float u = __uint_as_float((bits >> 9) | 0x3f800000u) - 1.0f;
    const float tiny = 1.17549435e-38f;
    float r = fmaxf(tiny, u + tiny);
    return -logf(-logf(r));
}
__device__ __forceinline__ float gelu_exact(float v) {
    return 0.5f * v * (1.0f + erff(v * 0.70710678118654752f));
}
__device__ __forceinline__ float softplus_f(float v) {
    return fmaxf(v, 0.f) + log1pf(expf(-fabsf(v)));
}

__global__ void k_graph(const float* __restrict__ w1, const float* __restrict__ b1,
                        const float* __restrict__ w2, const float* __restrict__ b2,
                        const float* __restrict__ pbeta, const float* __restrict__ pgamma,
                        const float* __restrict__ ptemp, float* __restrict__ outA) {
    __shared__ float sA[4096];
    __shared__ float sS[4096];
    __shared__ float ssq[64];
    __shared__ float sdinv[64];
    __shared__ unsigned long long smask[64];
    __shared__ float sw1[16], sb1[16], sw2[16];
    int tid = threadIdx.x;
    if (tid < 16) { sw1[tid] = w1[tid]; sb1[tid] = b1[tid]; sw2[tid] = w2[tid]; }
    float beta = *pbeta, gamma = *pgamma, b2v = *b2;
    float invt = 1.0f / fmaxf(*ptemp, 1e-6f);

#pragma unroll
    for (int k = 0; k < 16; k++) sS[tid + 256 * k] = g_Z[tid + 256 * k];
    __syncthreads();
    if (tid < 64) {
        float s = 0.f;
#pragma unroll
        for (int m = 0; m < 64; m++) { float z = sS[tid * 64 + m]; s += z * z; }
        ssq[tid] = s;
    }
    __syncthreads();

    float d2r[16];
#pragma unroll
    for (int k = 0; k < 16; k++) {
        int e = tid + 256 * k, i = e >> 6, j = e & 63;
        float dot = 0.f;
        for (int m = 0; m < 64; m++) dot += sS[i * 64 + m] * sS[j * 64 + m];
        float v = ssq[i] + ssq[j] - 2.0f * dot;
        d2r[k] = fmaxf(v, 0.f) * 0.5f;
        sA[e] = (i == j) ? 1.f : 0.f;
    }
    __syncthreads();

    for (int step = 0; step < 2; step++) {
#pragma unroll
        for (int k = 0; k < 16; k++) {
            int e = tid + 256 * k;
            float a = sA[e] - 0.2f * d2r[k];
            float s = b2v;
#pragma unroll
            for (int m = 0; m < 16; m++) {
                float h = gelu_exact(fmaf(a, sw1[m], sb1[m]));
                s = fmaf(h, sw2[m], s);
            }
            a = a + beta * (softplus_f(s) * gamma);
            sA[e] = a;
        }
        __syncthreads();
        float r1[16], r2[16];
#pragma unroll
        for (int k = 0; k < 16; k++) {
            int e = tid + 256 * k, i = e >> 6, j = e & 63;
            r1[k] = sA[e]; r2[k] = sA[j * 64 + i];
        }
        __syncthreads();
#pragma unroll
        for (int k = 0; k < 16; k++) {
            int e = tid + 256 * k, i = e >> 6, j = e & 63;
            float v = 0.5f * (r1[k] + r2[k]);
            sA[e] = fmaxf(v, 0.f) + ((i == j) ? 1.f : 0.f);
        }
        __syncthreads();
    }

#pragma unroll
    for (int k = 0; k < 16; k++) {
        int e = tid + 256 * k;
        sS[e] = (sA[e] + gumbel_at(e)) * invt;
    }
    __syncthreads();
    if (tid < 64) {
        float* row = sS + tid * 64;
        unsigned long long m = 0ull;
        for (int p = 0; p < 16; p++) {
            float best = -__int_as_float(0x7f800000);
            int bi = 0;
            for (int j = 0; j < 64; j++) {
                float v = row[j];
                if (v > best) { best = v; bi = j; }
            }
            row[bi] = __int_as_float(0xff800000);
            m |= (1ull << bi);
        }
        smask[tid] = m;
    }
    __syncthreads();
#pragma unroll
    for (int k = 0; k < 16; k++) {
        int e = tid + 256 * k, i = e >> 6, j = e & 63;
        if (!((smask[i] >> j) & 1ull)) sA[e] = 0.f;
    }
    __syncthreads();
    {
        float r1[16], r2[16];
#pragma unroll
        for (int k = 0; k < 16; k++) {
            int e = tid + 256 * k, i = e >> 6, j = e & 63;
            r1[k] = sA[e]; r2[k] = sA[j * 64 + i];
        }
        __syncthreads();
#pragma unroll
        for (int k = 0; k < 16; k++) {
            int e = tid + 256 * k, i = e >> 6, j = e & 63;
            float v = fmaxf(0.5f * (r1[k] + r2[k]), 0.f) + ((i == j) ? 1.f : 0.f);
            sA[e] = v;
        }
        __syncthreads();
    }
    if (tid < 64) {
        float s = 0.f;
        for (int j = 0; j < 64; j++) s += sA[tid * 64 + j];
        sdinv[tid] = rsqrtf(fmaxf(s, 1e-6f));
    }
    __syncthreads();
#pragma unroll
    for (int k = 0; k < 16; k++) {
        int e = tid + 256 * k, i = e >> 6, j = e & 63;
        float v = sdinv[i] * sA[e] * sdinv[j] + ((i == j) ? 1.f : 0.f);
        sA[e] = v;
        outA[e] = v;
    }
    __syncthreads();
    // A2 = A @ A (fuses the two propagation steps)
#pragma unroll
    for (int k = 0; k < 16; k++) {
        int e = tid + 256 * k, i = e >> 6, j = e & 63;
        float s = 0.f;
        for (int m = 0; m < 64; m++) s += sA[i * 64 + m] * sA[m * 64 + j];
        g_A2[e] = s;
    }
}

// ================= Kernel 4: out = A2 @ x =================
// Each thread: 8 channels (4 channel-pairs) x 8 consecutive t.
// Block: 8 warps = 8 channel-groups; lanes = 32 t-groups; covers 256 t of one bw.
// smem sp[c2][j] holds (A2[2c2][j], A2[2c2+1][j]) as f32x2; LDS.128 at even j
// fetches coefficient pairs for j and j+1 (no repack MOVs for coefficients).
__global__ void __launch_bounds__(256, 2) k_prop(const float* __restrict__ x,
                                                 float* __restrict__ out) {
    __shared__ __align__(16) unsigned long long sp[32 * 64];  // [c2][j]
    int tid = threadIdx.x;
#pragma unroll
    for (int k = 0; k < 8; k++) {
        int idx = tid + 256 * k;  // 0..2047
        int c2 = idx >> 6, j = idx & 63;
        sp[idx] = pack2(g_A2[(2 * c2) * 64 + j], g_A2[(2 * c2 + 1) * 64 + j]);
    }
    __syncthreads();

    int warp = tid >> 5, lane = tid & 31;
    int bw = blockIdx.x >> 2;
    int tbase = ((blockIdx.x & 3) << 8) + lane * 8;
    const float* xp = x + ((size_t)bw << 16) + tbase;
    const unsigned long long* spw = sp + (warp * 4) * 64;  // this warp's 4 ch-pairs

    unsigned long long acc[4][8];
#pragma unroll
    for (int c = 0; c < 4; c++)
#pragma unroll
        for (int t = 0; t < 8; t++) acc[c][t] = 0ull;

#pragma unroll 2
    for (int j2 = 0; j2 < 64; j2 += 2) {
        // coefficient pairs for j2 and j2+1, 4 channel-pairs
        ulonglong2 q0 = *reinterpret_cast<const ulonglong2*>(spw + 0 * 64 + j2);
        ulonglong2 q1 = *reinterpret_cast<const ulonglong2*>(spw + 1 * 64 + j2);
        ulonglong2 q2 = *reinterpret_cast<const ulonglong2*>(spw + 2 * 64 + j2);
        ulonglong2 q3 = *reinterpret_cast<const ulonglong2*>(spw + 3 * 64 + j2);
        {   // j = j2
            float4 xa = *reinterpret_cast<const float4*>(xp + ((size_t)j2 << 10));
            float4 xb = *reinterpret_cast<const float4*>(xp + ((size_t)j2 << 10) + 4);
            unsigned long long d0 = pack2(xa.x, xa.x), d1 = pack2(xa.y, xa.y);
            unsigned long long d2 = pack2(xa.z, xa.z), d3 = pack2(xa.w, xa.w);
            unsigned long long d4 = pack2(xb.x, xb.x), d5 = pack2(xb.y, xb.y);
            unsigned long long d6 = pack2(xb.z, xb.z), d7 = pack2(xb.w, xb.w);
            acc[0][0] = ffma2(q0.x, d0, acc[0][0]); acc[0][1] = ffma2(q0.x, d1, acc[0][1]);
            acc[0][2] = ffma2(q0.x, d2, acc[0][2]); acc[0][3] = ffma2(q0.x, d3, acc[0][3]);
            acc[0][4] = ffma2(q0.x, d4, acc[0][4]); acc[0][5] = ffma2(q0.x, d5, acc[0][5]);
            acc[0][6] = ffma2(q0.x, d6, acc[0][6]); acc[0][7] = ffma2(q0.x, d7, acc[0][7]);
            acc[1][0] = ffma2(q1.x, d0, acc[1][0]); acc[1][1] = ffma2(q1.x, d1, acc[1][1]);
            acc[1][2] = ffma2(q1.x, d2, acc[1][2]); acc[1][3] = ffma2(q1.x, d3, acc[1][3]);
            acc[1][4] = ffma2(q1.x, d4, acc[1][4]); acc[1][5] = ffma2(q1.x, d5, acc[1][5]);
            acc[1][6] = ffma2(q1.x, d6, acc[1][6]); acc[1][7] = ffma2(q1.x, d7, acc[1][7]);
            acc[2][0] = ffma2(q2.x, d0, acc[2][0]); acc[2][1] = ffma2(q2.x, d1, acc[2][1]);
            acc[2][2] = ffma2(q2.x, d2, acc[2][2]); acc[2][3] = ffma2(q2.x, d3, acc[2][3]);
            acc[2][4] = ffma2(q2.x, d4, acc[2][4]); acc[2][5] = ffma2(q2.x, d5, acc[2][5]);
            acc[2][6] = ffma2(q2.x, d6, acc[2][6]); acc[2][7] = ffma2(q2.x, d7, acc[2][7]);
            acc[3][0] = ffma2(q3.x, d0, acc[3][0]); acc[3][1] = ffma2(q3.x, d1, acc[3][1]);
            acc[3][2] = ffma2(q3.x, d2, acc[3][2]); acc[3][3] = ffma2(q3.x, d3, acc[3][3]);
            acc[3][4] = ffma2(q3.x, d4, acc[3][4]); acc[3][5] = ffma2(q3.x, d5, acc[3][5]);
            acc[3][6] = ffma2(q3.x, d6, acc[3][6]); acc[3][7] = ffma2(q3.x, d7, acc[3][7]);
        }
        {   // j = j2 + 1
            float4 xa = *reinterpret_cast<const float4*>(xp + ((size_t)(j2 + 1) << 10));
            float4 xb = *reinterpret_cast<const float4*>(xp + ((size_t)(j2 + 1) << 10) + 4);
            unsigned long long d0 = pack2(xa.x, xa.x), d1 = pack2(xa.y, xa.y);
            unsigned long long d2 = pack2(xa.z, xa.z), d3 = pack2(xa.w, xa.w);
            unsigned long long d4 = pack2(xb.x, xb.x), d5 = pack2(xb.y, xb.y);
            unsigned long long d6 = pack2(xb.z, xb.z), d7 = pack2(xb.w, xb.w);
            acc[0][0] = ffma2(q0.y, d0, acc[0][0]); acc[0][1] = ffma2(q0.y, d1, acc[0][1]);
            acc[0][2] = ffma2(q0.y, d2, acc[0][2]); acc[0][3] = ffma2(q0.y, d3, acc[0][3]);
            acc[0][4] = ffma2(q0.y, d4, acc[0][4]); acc[0][5] = ffma2(q0.y, d5, acc[0][5]);
            acc[0][6] = ffma2(q0.y, d6, acc[0][6]); acc[0][7] = ffma2(q0.y, d7, acc[0][7]);
            acc[1][0] = ffma2(q1.y, d0, acc[1][0]); acc[1][1] = ffma2(q1.y, d1, acc[1][1]);
            acc[1][2] = ffma2(q1.y, d2, acc[1][2]); acc[1][3] = ffma2(q1.y, d3, acc[1][3]);
            acc[1][4] = ffma2(q1.y, d4, acc[1][4]); acc[1][5] = ffma2(q1.y, d5, acc[1][5]);
            acc[1][6] = ffma2(q1.y, d6, acc[1][6]); acc[1][7] = ffma2(q1.y, d7, acc[1][7]);
            acc[2][0] = ffma2(q2.y, d0, acc[2][0]); acc[2][1] = ffma2(q2.y, d1, acc[2][1]);
            acc[2][2] = ffma2(q2.y, d2, acc[2][2]); acc[2][3] = ffma2(q2.y, d3, acc[2][3]);
            acc[2][4] = ffma2(q2.y, d4, acc[2][4]); acc[2][5] = ffma2(q2.y, d5, acc[2][5]);
            acc[2][6] = ffma2(q2.y, d6, acc[2][6]); acc[2][7] = ffma2(q2.y, d7, acc[2][7]);
            acc[3][0] = ffma2(q3.y, d0, acc[3][0]); acc[3][1] = ffma2(q3.y, d1, acc[3][1]);
            acc[3][2] = ffma2(q3.y, d2, acc[3][2]); acc[3][3] = ffma2(q3.y, d3, acc[3][3]);
            acc[3][4] = ffma2(q3.y, d4, acc[3][4]); acc[3][5] = ffma2(q3.y, d5, acc[3][5]);
            acc[3][6] = ffma2(q3.y, d6, acc[3][6]); acc[3][7] = ffma2(q3.y, d7, acc[3][7]);
        }
    }

    // epilogue: out[b][c][w*1024 + t], c = warp*8 + 2*c2 + {0,1}, t = tbase..tbase+7
    int b = bw >> 4, w = bw & 15;
    float* op = out + (size_t)b * 1048576 + (size_t)w * 1024 + tbase;
#pragma unroll
    for (int c2 = 0; c2 < 4; c2++) {
        int ch0 = warp * 8 + 2 * c2;
        float f0[8], f1[8];
#pragma unroll
        for (int t = 0; t < 8; t++) unpack2(acc[c2][t], f0[t], f1[t]);
        float4* p0 = reinterpret_cast<float4*>(op + (size_t)ch0 * 16384);
        float4* p1 = reinterpret_cast<float4*>(op + (size_t)(ch0 + 1) * 16384);
        p0[0] = make_float4(f0[0], f0[1], f0[2], f0[3]);
        p0[1] = make_float4(f0[4], f0[5], f0[6], f0[7]);
        p1[0] = make_float4(f1[0], f1[1], f1[2], f1[3]);
        p1[1] = make_float4(f1[4], f1[5], f1[6], f1[7]);
    }
}

// ================= launch =================
extern "C" void kernel_launch(void* const* d_in, const int* in_sizes, int n_in,
                              void* d_out, int out_size) {
    const float* x     = (const float*)d_in[0];
    const float* Wp    = (const float*)d_in[1];
    const float* w1    = (const float*)d_in[2];
    const float* b1    = (const float*)d_in[3];
    const float* w2    = (const float*)d_in[4];
    const float* b2    = (const float*)d_in[5];
    const float* beta  = (const float*)d_in[6];
    const float* gamma = (const float*)d_in[7];
    const float* temp  = (const float*)d_in[8];
    float* out = (float*)d_out;

    k_stats<<<8192, 256>>>(x);
    k_zmean<<<64, 256>>>(Wp);
    k_graph<<<1, 256>>>(w1, b1, w2, b2, beta, gamma, temp, out + XR_ELEMS);
    k_prop<<<4096, 256>>>(x, out);
}

// round 7
// speedup vs baseline: 1.7857x; 1.2423x over previous
#include <cuda_runtime.h>
#include <math.h>

// Problem constants
#define BB 64
#define WW 16
#define CC 64
#define TT 1024
#define DE 64
#define NBW 1024           // B*W
#define NROWS 65536        // B*W*C
#define XR_ELEMS 67108864  // B*C*W*T

// -------- device scratch (no allocations allowed) --------
__device__ float g_stat[NROWS];   // [bw][c]
__device__ float g_Z[CC * DE];    // [c][d]
__device__ float g_A2[CC * CC];   // A_final @ A_final

// -------- f32x2 helpers --------
__device__ __forceinline__ unsigned long long pack2(float a, float b) {
    unsigned long long r;
    asm("mov.b64 %0, {%1, %2};" : "=l"(r) : "f"(a), "f"(b));
    return r;
}
__device__ __forceinline__ unsigned long long ffma2(unsigned long long a,
                                                    unsigned long long b,
                                                    unsigned long long c) {
    unsigned long long d;
    asm("fma.rn.f32x2 %0, %1, %2, %3;" : "=l"(d) : "l"(a), "l"(b), "l"(c));
    return d;
}
__device__ __forceinline__ void unpack2(unsigned long long v, float& a, float& b) {
    asm("mov.b64 {%0, %1}, %2;" : "=f"(a), "=f"(b) : "l"(v));
}

// ================= Kernel 1: per-row stats =================
__global__ void k_stats(const float* __restrict__ x) {
    int warp = (blockIdx.x * blockDim.x + threadIdx.x) >> 5;
    int lane = threadIdx.x & 31;
    if (warp >= NROWS) return;
    const float4* p = reinterpret_cast<const float4*>(x) + (size_t)warp * 256;
    float s1 = 0.f, s2 = 0.f;
#pragma unroll
    for (int k = 0; k < 8; k++) {
        float4 v = p[lane + 32 * k];
        s1 += (v.x + v.y) + (v.z + v.w);
        s2 += v.x * v.x + v.y * v.y + v.z * v.z + v.w * v.w;
    }
#pragma unroll
    for (int off = 16; off > 0; off >>= 1) {
        s1 += __shfl_xor_sync(0xffffffffu, s1, off);
        s2 += __shfl_xor_sync(0xffffffffu, s2, off);
    }
    if (lane == 0) g_stat[warp] = 0.5f * (s1 + s2) * (1.0f / 1024.0f);
}

// ================= Kernel 2: Z_mean[c][d] =================
__global__ void k_zmean(const float* __restrict__ Wp) {
    __shared__ float scol[NBW];
    __shared__ float swp[DE];
    __shared__ float part[256];
    int c = blockIdx.x;
    int tid = threadIdx.x;
    if (tid < DE) swp[tid] = Wp[tid];
    for (int i = tid; i < NBW; i += 256) scol[i] = g_stat[i * CC + c];
    __syncthreads();
    int d = tid & 63, grp = tid >> 6;
    float w = swp[d];
    float s = 0.f;
    for (int bw = grp; bw < NBW; bw += 4) s += tanhf(scol[bw] * w);
    part[tid] = s;
    __syncthreads();
    if (tid < 64) {
        float z = (part[tid] + part[tid + 64] + part[tid + 128] + part[tid + 192]) *
                  (1.0f / 1024.0f);
        g_Z[c * DE + tid] = z;
    }
}

// ================= Kernel 3: graph build (single block, 1024 thr) =================
__device__ __forceinline__ unsigned rotl32(unsigned v, int s) {
    return (v << s) | (v >> (32 - s));
}
__device__ __forceinline__ void threefry_0_42(unsigned c0, unsigned c1,
                                              unsigned& o0, unsigned& o1) {
    const unsigned ks0 = 0u, ks1 = 42u, ks2 = 0u ^ 42u ^ 0x1BD11BDAu;
    unsigned x0 = c0 + ks0, x1 = c1 + ks1;
#define TF_RND(r) { x0 += x1; x1 = rotl32(x1, r); x1 ^= x0; }
    TF_RND(13) TF_RND(15) TF_RND(26) TF_RND(6)  x0 += ks1; x1 += ks2 + 1u;
    TF_RND(17) TF_RND(29) TF_RND(16) TF_RND(24) x0 += ks2; x1 += ks0 + 2u;
    TF_RND(13) TF_RND(15) TF_RND(26) TF_RND(6)  x0 += ks0; x1 += ks1 + 3u;
    TF_RND(17) TF_RND(29) TF_RND(16) TF_RND(24) x0 += ks1; x1 += ks2 + 4u;
    TF_RND(13) TF_RND(15) TF_RND(26) TF_RND(6)  x0 += ks2; x1 += ks0 + 5u;
#undef TF_RND
    o0 = x0; o1 = x1;
}
// Partitionable threefry: counter (0, idx); sample = XOR-fold of output words.
__device__ __forceinline__ float gumbel_at(int idx) {
    unsigned o0, o1;
    threefry_0_42(0u, (unsigned)idx, o0, o1);
    unsigned bits = o0 ^ o1;
    float u = __uint_as_float((bits >> 9) | 0x3f800000u) - 1.0f;
    const float tiny = 1.17549435e-38f;
    float r = fmaxf(tiny, u + tiny);
    return -logf(-logf(r));
}
__device__ __forceinline__ float gelu_exact(float v) {
    return 0.5f * v * (1.0f + erff(v * 0.70710678118654752f));
}
__device__ __forceinline__ float softplus_f(float v) {
    return fmaxf(v, 0.f) + log1pf(expf(-fabsf(v)));
}

#define GNT 1024   // threads in k_graph
#define EPT 4      // elems per thread (4096 / 1024)

__global__ void __launch_bounds__(GNT) k_graph(
        const float* __restrict__ w1, const float* __restrict__ b1,
        const float* __restrict__ w2, const float* __restrict__ b2,
        const float* __restrict__ pbeta, const float* __restrict__ pgamma,
        const float* __restrict__ ptemp, float* __restrict__ outA) {
    __shared__ float sA[4096];
    __shared__ float sS[4096];
    __shared__ float ssq[64];
    __shared__ float sdinv[64];
    __shared__ unsigned long long smask[64];
    __shared__ float sw1[16], sb1[16], sw2[16];
    int tid = threadIdx.x;
    if (tid < 16) { sw1[tid] = w1[tid]; sb1[tid] = b1[tid]; sw2[tid] = w2[tid]; }
    float beta = *pbeta, gamma = *pgamma, b2v = *b2;
    float invt = 1.0f / fmaxf(*ptemp, 1e-6f);

#pragma unroll
    for (int k = 0; k < EPT; k++) sS[tid + GNT * k] = g_Z[tid + GNT * k];
    __syncthreads();
    if (tid < 64) {
        float s = 0.f;
#pragma unroll
        for (int m = 0; m < 64; m++) { float z = sS[tid * 64 + m]; s += z * z; }
        ssq[tid] = s;
    }
    __syncthreads();

    float d2r[EPT];
#pragma unroll
    for (int k = 0; k < EPT; k++) {
        int e = tid + GNT * k, i = e >> 6, j = e & 63;
        float dot = 0.f;
        for (int m = 0; m < 64; m++) dot += sS[i * 64 + m] * sS[j * 64 + m];
        float v = ssq[i] + ssq[j] - 2.0f * dot;
        d2r[k] = fmaxf(v, 0.f) * 0.5f;
        sA[e] = (i == j) ? 1.f : 0.f;
    }
    __syncthreads();

    for (int step = 0; step < 2; step++) {
#pragma unroll
        for (int k = 0; k < EPT; k++) {
            int e = tid + GNT * k;
            float a = sA[e] - 0.2f * d2r[k];
            float s = b2v;
#pragma unroll
            for (int m = 0; m < 16; m++) {
                float h = gelu_exact(fmaf(a, sw1[m], sb1[m]));
                s = fmaf(h, sw2[m], s);
            }
            a = a + beta * (softplus_f(s) * gamma);
            sA[e] = a;
        }
        __syncthreads();
        float r1[EPT], r2[EPT];
#pragma unroll
        for (int k = 0; k < EPT; k++) {
            int e = tid + GNT * k, i = e >> 6, j = e & 63;
            r1[k] = sA[e]; r2[k] = sA[j * 64 + i];
        }
        __syncthreads();
#pragma unroll
        for (int k = 0; k < EPT; k++) {
            int e = tid + GNT * k, i = e >> 6, j = e & 63;
            float v = 0.5f * (r1[k] + r2[k]);
            sA[e] = fmaxf(v, 0.f) + ((i == j) ? 1.f : 0.f);
        }
        __syncthreads();
    }

    // Gumbel scores
#pragma unroll
    for (int k = 0; k < EPT; k++) {
        int e = tid + GNT * k;
        sS[e] = (sA[e] + gumbel_at(e)) * invt;
    }
    __syncthreads();

    // Warp-parallel top-16 per row. 32 warps, 2 rows each.
    // Tie-break: lowest index (matches serial first-max scan).
    {
        int warp = tid >> 5, lane = tid & 31;
        const float NEG_INF = __int_as_float(0xff800000);
#pragma unroll
        for (int rr = 0; rr < 2; rr++) {
            int r = warp * 2 + rr;
            float v0 = sS[r * 64 + lane];
            float v1 = sS[r * 64 + 32 + lane];
            bool p0 = false, p1 = false;
            for (int p = 0; p < 16; p++) {
                float bv; int bi;
                if (v0 >= v1) { bv = v0; bi = lane; }
                else          { bv = v1; bi = lane + 32; }
#pragma unroll
                for (int off = 16; off > 0; off >>= 1) {
                    float ov = __shfl_xor_sync(0xffffffffu, bv, off);
                    int   oi = __shfl_xor_sync(0xffffffffu, bi, off);
                    if (ov > bv || (ov == bv && oi < bi)) { bv = ov; bi = oi; }
                }
                if (bi == lane)           { p0 = true; v0 = NEG_INF; }
                else if (bi == lane + 32) { p1 = true; v1 = NEG_INF; }
            }
            unsigned lo = __ballot_sync(0xffffffffu, p0);
            unsigned hi = __ballot_sync(0xffffffffu, p1);
            if (lane == 0)
                smask[r] = (unsigned long long)lo | ((unsigned long long)hi << 32);
        }
    }
    __syncthreads();
#pragma unroll
    for (int k = 0; k < EPT; k++) {
        int e = tid + GNT * k, i = e >> 6, j = e & 63;
        if (!((smask[i] >> j) & 1ull)) sA[e] = 0.f;
    }
    __syncthreads();
    {
        float r1[EPT], r2[EPT];
#pragma unroll
        for (int k = 0; k < EPT; k++) {
            int e = tid + GNT * k, i = e >> 6, j = e & 63;
            r1[k] = sA[e]; r2[k] = sA[j * 64 + i];
        }
        __syncthreads();
#pragma unroll
        for (int k = 0; k < EPT; k++) {
            int e = tid + GNT * k, i = e >> 6, j = e & 63;
            float v = fmaxf(0.5f * (r1[k] + r2[k]), 0.f) + ((i == j) ? 1.f : 0.f);
            sA[e] = v;
        }
        __syncthreads();
    }
    if (tid < 64) {
        float s = 0.f;
        for (int j = 0; j < 64; j++) s += sA[tid * 64 + j];
        sdinv[tid] = rsqrtf(fmaxf(s, 1e-6f));
    }
    __syncthreads();
#pragma unroll
    for (int k = 0; k < EPT; k++) {
        int e = tid + GNT * k, i = e >> 6, j = e & 63;
        float v = sdinv[i] * sA[e] * sdinv[j] + ((i == j) ? 1.f : 0.f);
        sA[e] = v;
        outA[e] = v;
    }
    __syncthreads();
    // A2 = A @ A (fuses the two propagation steps)
#pragma unroll
    for (int k = 0; k < EPT; k++) {
        int e = tid + GNT * k, i = e >> 6, j = e & 63;
        float s = 0.f;
        for (int m = 0; m < 64; m++) s += sA[i * 64 + m] * sA[m * 64 + j];
        g_A2[e] = s;
    }
}

// ================= Kernel 4: out = A2 @ x =================
// Thread: 8 channels (4 ch-pairs) x 8 consecutive t. Loads for both j's hoisted
// before any FMA (MLP=4 LDG in flight) + L2 prefetch 2 rows ahead.
__global__ void __launch_bounds__(256, 2) k_prop(const float* __restrict__ x,
                                                 float* __restrict__ out) {
    __shared__ __align__(16) unsigned long long sp[32 * 64];  // [c2][j]
    int tid = threadIdx.x;
#pragma unroll
    for (int k = 0; k < 8; k++) {
        int idx = tid + 256 * k;  // 0..2047
        int c2 = idx >> 6, j = idx & 63;
        sp[idx] = pack2(g_A2[(2 * c2) * 64 + j], g_A2[(2 * c2 + 1) * 64 + j]);
    }
    __syncthreads();

    int warp = tid >> 5, lane = tid & 31;
    int bw = blockIdx.x >> 2;
    int tbase = ((blockIdx.x & 3) << 8) + lane * 8;
    const float* xp = x + ((size_t)bw << 16) + tbase;
    const unsigned long long* spw = sp + (warp * 4) * 64;

    unsigned long long acc[4][8];
#pragma unroll
    for (int c = 0; c < 4; c++)
#pragma unroll
        for (int t = 0; t < 8; t++) acc[c][t] = 0ull;

#pragma unroll 2
    for (int j2 = 0; j2 < 64; j2 += 2) {
        const float* xr0 = xp + ((size_t)j2 << 10);
        const float* xr1 = xr0 + 1024;
        // issue all global loads first (4 LDG.128 in flight)
        float4 xa0 = *reinterpret_cast<const float4*>(xr0);
        float4 xb0 = *reinterpret_cast<const float4*>(xr0 + 4);
        float4 xa1 = *reinterpret_cast<const float4*>(xr1);
        float4 xb1 = *reinterpret_cast<const float4*>(xr1 + 4);
        // prefetch rows j2+2, j2+3 into L2 (register-free)
        if (j2 < 62) {
            asm volatile("prefetch.global.L2 [%0];" :: "l"(xr0 + 2048));
            asm volatile("prefetch.global.L2 [%0];" :: "l"(xr1 + 2048));
        }
        // coefficient pairs for j2 / j2+1, 4 channel-pairs
        ulonglong2 q0 = *reinterpret_cast<const ulonglong2*>(spw + 0 * 64 + j2);
        ulonglong2 q1 = *reinterpret_cast<const ulonglong2*>(spw + 1 * 64 + j2);
        ulonglong2 q2 = *reinterpret_cast<const ulonglong2*>(spw + 2 * 64 + j2);
        ulonglong2 q3 = *reinterpret_cast<const ulonglong2*>(spw + 3 * 64 + j2);
        {   // j = j2
            unsigned long long d0 = pack2(xa0.x, xa0.x), d1 = pack2(xa0.y, xa0.y);
            unsigned long long d2 = pack2(xa0.z, xa0.z), d3 = pack2(xa0.w, xa0.w);
            unsigned long long d4 = pack2(xb0.x, xb0.x), d5 = pack2(xb0.y, xb0.y);
            unsigned long long d6 = pack2(xb0.z, xb0.z), d7 = pack2(xb0.w, xb0.w);
            acc[0][0] = ffma2(q0.x, d0, acc[0][0]); acc[0][1] = ffma2(q0.x, d1, acc[0][1]);
            acc[0][2] = ffma2(q0.x, d2, acc[0][2]); acc[0][3] = ffma2(q0.x, d3, acc[0][3]);
            acc[0][4] = ffma2(q0.x, d4, acc[0][4]); acc[0][5] = ffma2(q0.x, d5, acc[0][5]);
            acc[0][6] = ffma2(q0.x, d6, acc[0][6]); acc[0][7] = ffma2(q0.x, d7, acc[0][7]);
            acc[1][0] = ffma2(q1.x, d0, acc[1][0]); acc[1][1] = ffma2(q1.x, d1, acc[1][1]);
            acc[1][2] = ffma2(q1.x, d2, acc[1][2]); acc[1][3] = ffma2(q1.x, d3, acc[1][3]);
            acc[1][4] = ffma2(q1.x, d4, acc[1][4]); acc[1][5] = ffma2(q1.x, d5, acc[1][5]);
            acc[1][6] = ffma2(q1.x, d6, acc[1][6]); acc[1][7] = ffma2(q1.x, d7, acc[1][7]);
            acc[2][0] = ffma2(q2.x, d0, acc[2][0]); acc[2][1] = ffma2(q2.x, d1, acc[2][1]);
            acc[2][2] = ffma2(q2.x, d2, acc[2][2]); acc[2][3] = ffma2(q2.x, d3, acc[2][3]);
            acc[2][4] = ffma2(q2.x, d4, acc[2][4]); acc[2][5] = ffma2(q2.x, d5, acc[2][5]);
            acc[2][6] = ffma2(q2.x, d6, acc[2][6]); acc[2][7] = ffma2(q2.x, d7, acc[2][7]);
            acc[3][0] = ffma2(q3.x, d0, acc[3][0]); acc[3][1] = ffma2(q3.x, d1, acc[3][1]);
            acc[3][2] = ffma2(q3.x, d2, acc[3][2]); acc[3][3] = ffma2(q3.x, d3, acc[3][3]);
            acc[3][4] = ffma2(q3.x, d4, acc[3][4]); acc[3][5] = ffma2(q3.x, d5, acc[3][5]);
            acc[3][6] = ffma2(q3.x, d6, acc[3][6]); acc[3][7] = ffma2(q3.x, d7, acc[3][7]);
        }
        {   // j = j2 + 1
            unsigned long long d0 = pack2(xa1.x, xa1.x), d1 = pack2(xa1.y, xa1.y);
            unsigned long long d2 = pack2(xa1.z, xa1.z), d3 = pack2(xa1.w, xa1.w);
            unsigned long long d4 = pack2(xb1.x, xb1.x), d5 = pack2(xb1.y, xb1.y);
            unsigned long long d6 = pack2(xb1.z, xb1.z), d7 = pack2(xb1.w, xb1.w);
            acc[0][0] = ffma2(q0.y, d0, acc[0][0]); acc[0][1] = ffma2(q0.y, d1, acc[0][1]);
            acc[0][2] = ffma2(q0.y, d2, acc[0][2]); acc[0][3] = ffma2(q0.y, d3, acc[0][3]);
            acc[0][4] = ffma2(q0.y, d4, acc[0][4]); acc[0][5] = ffma2(q0.y, d5, acc[0][5]);
            acc[0][6] = ffma2(q0.y, d6, acc[0][6]); acc[0][7] = ffma2(q0.y, d7, acc[0][7]);
            acc[1][0] = ffma2(q1.y, d0, acc[1][0]); acc[1][1] = ffma2(q1.y, d1, acc[1][1]);
            acc[1][2] = ffma2(q1.y, d2, acc[1][2]); acc[1][3] = ffma2(q1.y, d3, acc[1][3]);
            acc[1][4] = ffma2(q1.y, d4, acc[1][4]); acc[1][5] = ffma2(q1.y, d5, acc[1][5]);
            acc[1][6] = ffma2(q1.y, d6, acc[1][6]); acc[1][7] = ffma2(q1.y, d7, acc[1][7]);
            acc[2][0] = ffma2(q2.y, d0, acc[2][0]); acc[2][1] = ffma2(q2.y, d1, acc[2][1]);
            acc[2][2] = ffma2(q2.y, d2, acc[2][2]); acc[2][3] = ffma2(q2.y, d3, acc[2][3]);
            acc[2][4] = ffma2(q2.y, d4, acc[2][4]); acc[2][5] = ffma2(q2.y, d5, acc[2][5]);
            acc[2][6] = ffma2(q2.y, d6, acc[2][6]); acc[2][7] = ffma2(q2.y, d7, acc[2][7]);
            acc[3][0] = ffma2(q3.y, d0, acc[3][0]); acc[3][1] = ffma2(q3.y, d1, acc[3][1]);
            acc[3][2] = ffma2(q3.y, d2, acc[3][2]); acc[3][3] = ffma2(q3.y, d3, acc[3][3]);
            acc[3][4] = ffma2(q3.y, d4, acc[3][4]); acc[3][5] = ffma2(q3.y, d5, acc[3][5]);
            acc[3][6] = ffma2(q3.y, d6, acc[3][6]); acc[3][7] = ffma2(q3.y, d7, acc[3][7]);
        }
    }

    // epilogue: out[b][c][w*1024 + t]
    int b = bw >> 4, w = bw & 15;
    float* op = out + (size_t)b * 1048576 + (size_t)w * 1024 + tbase;
#pragma unroll
    for (int c2 = 0; c2 < 4; c2++) {
        int ch0 = warp * 8 + 2 * c2;
        float f0[8], f1[8];
#pragma unroll
        for (int t = 0; t < 8; t++) unpack2(acc[c2][t], f0[t], f1[t]);
        float4* p0 = reinterpret_cast<float4*>(op + (size_t)ch0 * 16384);
        float4* p1 = reinterpret_cast<float4*>(op + (size_t)(ch0 + 1) * 16384);
        p0[0] = make_float4(f0[0], f0[1], f0[2], f0[3]);
        p0[1] = make_float4(f0[4], f0[5], f0[6], f0[7]);
        p1[0] = make_float4(f1[0], f1[1], f1[2], f1[3]);
        p1[1] = make_float4(f1[4], f1[5], f1[6], f1[7]);
    }
}

// ================= launch =================
extern "C" void kernel_launch(void* const* d_in, const int* in_sizes, int n_in,
                              void* d_out, int out_size) {
    const float* x     = (const float*)d_in[0];
    const float* Wp    = (const float*)d_in[1];
    const float* w1    = (const float*)d_in[2];
    const float* b1    = (const float*)d_in[3];
    const float* w2    = (const float*)d_in[4];
    const float* b2    = (const float*)d_in[5];
    const float* beta  = (const float*)d_in[6];
    const float* gamma = (const float*)d_in[7];
    const float* temp  = (const float*)d_in[8];
    float* out = (float*)d_out;

    k_stats<<<8192, 256>>>(x);
    k_zmean<<<64, 256>>>(Wp);
    k_graph<<<1, GNT>>>(w1, b1, w2, b2, beta, gamma, temp, out + XR_ELEMS);
    k_prop<<<4096, 256>>>(x, out);
}

// round 8
// speedup vs baseline: 1.9545x; 1.0945x over previous
#include <cuda_runtime.h>
#include <math.h>

// Problem constants
#define BB 64
#define WW 16
#define CC 64
#define TT 1024
#define DE 64
#define NBW 1024           // B*W
#define NROWS 65536        // B*W*C
#define XR_ELEMS 67108864  // B*C*W*T

// -------- device scratch (no allocations allowed) --------
__device__ float g_stat[NROWS];   // [bw][c]
__device__ float g_Z[CC * DE];    // [c][d]
__device__ float g_A2[CC * CC];   // A_final @ A_final

// -------- f32x2 helpers --------
__device__ __forceinline__ unsigned long long pack2(float a, float b) {
    unsigned long long r;
    asm("mov.b64 %0, {%1, %2};" : "=l"(r) : "f"(a), "f"(b));
    return r;
}
__device__ __forceinline__ unsigned long long ffma2(unsigned long long a,
                                                    unsigned long long b,
                                                    unsigned long long c) {
    unsigned long long d;
    asm("fma.rn.f32x2 %0, %1, %2, %3;" : "=l"(d) : "l"(a), "l"(b), "l"(c));
    return d;
}
__device__ __forceinline__ void unpack2(unsigned long long v, float& a, float& b) {
    asm("mov.b64 {%0, %1}, %2;" : "=f"(a), "=f"(b) : "l"(v));
}
__device__ __forceinline__ unsigned smem_u32(const void* p) {
    unsigned a;
    asm("{ .reg .u64 t; cvta.to.shared.u64 t, %1; cvt.u32.u64 %0, t; }"
        : "=r"(a) : "l"(p));
    return a;
}
__device__ __forceinline__ void cp_async16(unsigned dst, const void* src) {
    asm volatile("cp.async.cg.shared.global [%0], [%1], 16;" :: "r"(dst), "l"(src));
}
#define CP_COMMIT() asm volatile("cp.async.commit_group;")
#define CP_WAIT(N)  asm volatile("cp.async.wait_group %0;" :: "n"(N))

// ================= Kernel 1: per-row stats =================
__global__ void k_stats(const float* __restrict__ x) {
    int warp = (blockIdx.x * blockDim.x + threadIdx.x) >> 5;
    int lane = threadIdx.x & 31;
    if (warp >= NROWS) return;
    const float4* p = reinterpret_cast<const float4*>(x) + (size_t)warp * 256;
    float s1 = 0.f, s2 = 0.f;
#pragma unroll
    for (int k = 0; k < 8; k++) {
        float4 v = p[lane + 32 * k];
        s1 += (v.x + v.y) + (v.z + v.w);
        s2 += v.x * v.x + v.y * v.y + v.z * v.z + v.w * v.w;
    }
#pragma unroll
    for (int off = 16; off > 0; off >>= 1) {
        s1 += __shfl_xor_sync(0xffffffffu, s1, off);
        s2 += __shfl_xor_sync(0xffffffffu, s2, off);
    }
    if (lane == 0) g_stat[warp] = 0.5f * (s1 + s2) * (1.0f / 1024.0f);
}

// ================= Kernel 2: Z_mean[c][d] =================
__global__ void k_zmean(const float* __restrict__ Wp) {
    __shared__ float scol[NBW];
    __shared__ float swp[DE];
    __shared__ float part[256];
    int c = blockIdx.x;
    int tid = threadIdx.x;
    if (tid < DE) swp[tid] = Wp[tid];
    for (int i = tid; i < NBW; i += 256) scol[i] = g_stat[i * CC + c];
    __syncthreads();
    int d = tid & 63, grp = tid >> 6;
    float w = swp[d];
    float s = 0.f;
    for (int bw = grp; bw < NBW; bw += 4) s += tanhf(scol[bw] * w);
    part[tid] = s;
    __syncthreads();
    if (tid < 64) {
        float z = (part[tid] + part[tid + 64] + part[tid + 128] + part[tid + 192]) *
                  (1.0f / 1024.0f);
        g_Z[c * DE + tid] = z;
    }
}

// ================= Kernel 3: graph build (single block, 1024 thr) =================
__device__ __forceinline__ unsigned rotl32(unsigned v, int s) {
    return (v << s) | (v >> (32 - s));
}
__device__ __forceinline__ void threefry_0_42(unsigned c0, unsigned c1,
                                              unsigned& o0, unsigned& o1) {
    const unsigned ks0 = 0u, ks1 = 42u, ks2 = 0u ^ 42u ^ 0x1BD11BDAu;
    unsigned x0 = c0 + ks0, x1 = c1 + ks1;
#define TF_RND(r) { x0 += x1; x1 = rotl32(x1, r); x1 ^= x0; }
    TF_RND(13) TF_RND(15) TF_RND(26) TF_RND(6)  x0 += ks1; x1 += ks2 + 1u;
    TF_RND(17) TF_RND(29) TF_RND(16) TF_RND(24) x0 += ks2; x1 += ks0 + 2u;
    TF_RND(13) TF_RND(15) TF_RND(26) TF_RND(6)  x0 += ks0; x1 += ks1 + 3u;
    TF_RND(17) TF_RND(29) TF_RND(16) TF_RND(24) x0 += ks1; x1 += ks2 + 4u;
    TF_RND(13) TF_RND(15) TF_RND(26) TF_RND(6)  x0 += ks2; x1 += ks0 + 5u;
#undef TF_RND
    o0 = x0; o1 = x1;
}
// Partitionable threefry: counter (0, idx); sample = XOR-fold of output words.
__device__ __forceinline__ float gumbel_at(int idx) {
    unsigned o0, o1;
    threefry_0_42(0u, (unsigned)idx, o0, o1);
    unsigned bits = o0 ^ o1;
    float u = __uint_as_float((bits >> 9) | 0x3f800000u) - 1.0f;
    const float tiny = 1.17549435e-38f;
    float r = fmaxf(tiny, u + tiny);
    return -logf(-logf(r));
}
__device__ __forceinline__ float gelu_exact(float v) {
    return 0.5f * v * (1.0f + erff(v * 0.70710678118654752f));
}
__device__ __forceinline__ float softplus_f(float v) {
    return fmaxf(v, 0.f) + log1pf(expf(-fabsf(v)));
}

#define GNT 1024   // threads in k_graph
#define EPT 4      // elems per thread (4096 / 1024)

__global__ void __launch_bounds__(GNT) k_graph(
        const float* __restrict__ w1, const float* __restrict__ b1,
        const float* __restrict__ w2, const float* __restrict__ b2,
        const float* __restrict__ pbeta, const float* __restrict__ pgamma,
        const float* __restrict__ ptemp, float* __restrict__ outA) {
    __shared__ float sA[4096];
    __shared__ float sS[4096];
    __shared__ float ssq[64];
    __shared__ float sdinv[64];
    __shared__ unsigned long long smask[64];
    __shared__ float sw1[16], sb1[16], sw2[16];
    int tid = threadIdx.x;
    if (tid < 16) { sw1[tid] = w1[tid]; sb1[tid] = b1[tid]; sw2[tid] = w2[tid]; }
    float beta = *pbeta, gamma = *pgamma, b2v = *b2;
    float invt = 1.0f / fmaxf(*ptemp, 1e-6f);

#pragma unroll
    for (int k = 0; k < EPT; k++) sS[tid + GNT * k] = g_Z[tid + GNT * k];
    __syncthreads();
    if (tid < 64) {
        float s = 0.f;
#pragma unroll
        for (int m = 0; m < 64; m++) { float z = sS[tid * 64 + m]; s += z * z; }
        ssq[tid] = s;
    }
    __syncthreads();

    float d2r[EPT];
#pragma unroll
    for (int k = 0; k < EPT; k++) {
        int e = tid + GNT * k, i = e >> 6, j = e & 63;
        float dot = 0.f;
        for (int m = 0; m < 64; m++) dot += sS[i * 64 + m] * sS[j * 64 + m];
        float v = ssq[i] + ssq[j] - 2.0f * dot;
        d2r[k] = fmaxf(v, 0.f) * 0.5f;
        sA[e] = (i == j) ? 1.f : 0.f;
    }
    __syncthreads();

    for (int step = 0; step < 2; step++) {
#pragma unroll
        for (int k = 0; k < EPT; k++) {
            int e = tid + GNT * k;
            float a = sA[e] - 0.2f * d2r[k];
            float s = b2v;
#pragma unroll
            for (int m = 0; m < 16; m++) {
                float h = gelu_exact(fmaf(a, sw1[m], sb1[m]));
                s = fmaf(h, sw2[m], s);
            }
            a = a + beta * (softplus_f(s) * gamma);
            sA[e] = a;
        }
        __syncthreads();
        float r1[EPT], r2[EPT];
#pragma unroll
        for (int k = 0; k < EPT; k++) {
            int e = tid + GNT * k, i = e >> 6, j = e & 63;
            r1[k] = sA[e]; r2[k] = sA[j * 64 + i];
        }
        __syncthreads();
#pragma unroll
        for (int k = 0; k < EPT; k++) {
            int e = tid + GNT * k, i = e >> 6, j = e & 63;
            float v = 0.5f * (r1[k] + r2[k]);
            sA[e] = fmaxf(v, 0.f) + ((i == j) ? 1.f : 0.f);
        }
        __syncthreads();
    }

    // Gumbel scores
#pragma unroll
    for (int k = 0; k < EPT; k++) {
        int e = tid + GNT * k;
        sS[e] = (sA[e] + gumbel_at(e)) * invt;
    }
    __syncthreads();

    // Warp-parallel top-16 per row. 32 warps, 2 rows each.
    {
        int warp = tid >> 5, lane = tid & 31;
        const float NEG_INF = __int_as_float(0xff800000);
#pragma unroll
        for (int rr = 0; rr < 2; rr++) {
            int r = warp * 2 + rr;
            float v0 = sS[r * 64 + lane];
            float v1 = sS[r * 64 + 32 + lane];
            bool p0 = false, p1 = false;
            for (int p = 0; p < 16; p++) {
                float bv; int bi;
                if (v0 >= v1) { bv = v0; bi = lane; }
                else          { bv = v1; bi = lane + 32; }
#pragma unroll
                for (int off = 16; off > 0; off >>= 1) {
                    float ov = __shfl_xor_sync(0xffffffffu, bv, off);
                    int   oi = __shfl_xor_sync(0xffffffffu, bi, off);
                    if (ov > bv || (ov == bv && oi < bi)) { bv = ov; bi = oi; }
                }
                if (bi == lane)           { p0 = true; v0 = NEG_INF; }
                else if (bi == lane + 32) { p1 = true; v1 = NEG_INF; }
            }
            unsigned lo = __ballot_sync(0xffffffffu, p0);
            unsigned hi = __ballot_sync(0xffffffffu, p1);
            if (lane == 0)
                smask[r] = (unsigned long long)lo | ((unsigned long long)hi << 32);
        }
    }
    __syncthreads();
#pragma unroll
    for (int k = 0; k < EPT; k++) {
        int e = tid + GNT * k, i = e >> 6, j = e & 63;
        if (!((smask[i] >> j) & 1ull)) sA[e] = 0.f;
    }
    __syncthreads();
    {
        float r1[EPT], r2[EPT];
#pragma unroll
        for (int k = 0; k < EPT; k++) {
            int e = tid + GNT * k, i = e >> 6, j = e & 63;
            r1[k] = sA[e]; r2[k] = sA[j * 64 + i];
        }
        __syncthreads();
#pragma unroll
        for (int k = 0; k < EPT; k++) {
            int e = tid + GNT * k, i = e >> 6, j = e & 63;
            float v = fmaxf(0.5f * (r1[k] + r2[k]), 0.f) + ((i == j) ? 1.f : 0.f);
            sA[e] = v;
        }
        __syncthreads();
    }
    if (tid < 64) {
        float s = 0.f;
        for (int j = 0; j < 64; j++) s += sA[tid * 64 + j];
        sdinv[tid] = rsqrtf(fmaxf(s, 1e-6f));
    }
    __syncthreads();
#pragma unroll
    for (int k = 0; k < EPT; k++) {
        int e = tid + GNT * k, i = e >> 6, j = e & 63;
        float v = sdinv[i] * sA[e] * sdinv[j] + ((i == j) ? 1.f : 0.f);
        sA[e] = v;
        outA[e] = v;
    }
    __syncthreads();
    // A2 = A @ A (fuses the two propagation steps)
#pragma unroll
    for (int k = 0; k < EPT; k++) {
        int e = tid + GNT * k, i = e >> 6, j = e & 63;
        float s = 0.f;
        for (int m = 0; m < 64; m++) s += sA[i * 64 + m] * sA[m * 64 + j];
        g_A2[e] = s;
    }
}

// ================= Kernel 4: out = A2 @ x =================
// x tile (64 rows x 256 t = 64 KB) staged through smem with a double-buffered
// cp.async pipeline (4 chunks of 16 rows); inner loop is pure LDS + FFMA2.
#define JCH 16           // rows per chunk
#define NCH 4            // chunks (64 / 16)
#define CHF4 1024        // float4s per chunk (16*256/4)

__global__ void __launch_bounds__(256, 2) k_prop(const float* __restrict__ x,
                                                 float* __restrict__ out) {
    __shared__ __align__(16) unsigned long long sp[32 * 64];   // coeff pairs, 16 KB
    __shared__ __align__(16) float sx[2][JCH * 256];           // 2 x 16 KB
    int tid = threadIdx.x;
    int warp = tid >> 5, lane = tid & 31;
    int bw = blockIdx.x >> 2;
    int tgrp = (blockIdx.x & 3) << 8;
    const float* xbase = x + ((size_t)bw << 16) + tgrp;  // [row][256 t] view

    unsigned sx_addr = smem_u32(&sx[0][0]);

    // preload chunk 0 (rows 0..15)
#pragma unroll
    for (int k = 0; k < 4; k++) {
        int i = tid + 256 * k;            // float4 index 0..1023
        int row = i >> 6, c4 = i & 63;
        cp_async16(sx_addr + (unsigned)i * 16,
                   xbase + (size_t)row * 1024 + c4 * 4);
    }
    CP_COMMIT();

    // coefficient pairs: sp[c2][j] = (A2[2c2][j], A2[2c2+1][j])
#pragma unroll
    for (int k = 0; k < 8; k++) {
        int idx = tid + 256 * k;
        int c2 = idx >> 6, j = idx & 63;
        sp[idx] = pack2(g_A2[(2 * c2) * 64 + j], g_A2[(2 * c2 + 1) * 64 + j]);
    }

    const unsigned long long* spw = sp + (warp * 4) * 64;
    int tbase = tgrp + lane * 8;

    unsigned long long acc[4][8];
#pragma unroll
    for (int c = 0; c < 4; c++)
#pragma unroll
        for (int t = 0; t < 8; t++) acc[c][t] = 0ull;

#pragma unroll
    for (int ch = 0; ch < NCH; ch++) {
        if (ch + 1 < NCH) {   // issue next chunk into the other buffer
            unsigned dst = sx_addr + (unsigned)(((ch + 1) & 1) * CHF4) * 16;
            const float* src = xbase + (size_t)(ch + 1) * JCH * 1024;
#pragma unroll
            for (int k = 0; k < 4; k++) {
                int i = tid + 256 * k;
                int row = i >> 6, c4 = i & 63;
                cp_async16(dst + (unsigned)i * 16,
                           src + (size_t)row * 1024 + c4 * 4);
            }
            CP_COMMIT();
            CP_WAIT(1);
        } else {
            CP_WAIT(0);
        }
        __syncthreads();

        const float* xs = sx[ch & 1] + lane * 8;
#pragma unroll 2
        for (int jr = 0; jr < JCH; jr += 2) {
            int j2 = ch * JCH + jr;
            const float* xr0 = xs + jr * 256;
            const float* xr1 = xr0 + 256;
            float4 xa0 = *reinterpret_cast<const float4*>(xr0);
            float4 xb0 = *reinterpret_cast<const float4*>(xr0 + 4);
            float4 xa1 = *reinterpret_cast<const float4*>(xr1);
            float4 xb1 = *reinterpret_cast<const float4*>(xr1 + 4);
            ulonglong2 q0 = *reinterpret_cast<const ulonglong2*>(spw + 0 * 64 + j2);
            ulonglong2 q1 = *reinterpret_cast<const ulonglong2*>(spw + 1 * 64 + j2);
            ulonglong2 q2 = *reinterpret_cast<const ulonglong2*>(spw + 2 * 64 + j2);
            ulonglong2 q3 = *reinterpret_cast<const ulonglong2*>(spw + 3 * 64 + j2);
            {   // j = j2
                unsigned long long d0 = pack2(xa0.x, xa0.x), d1 = pack2(xa0.y, xa0.y);
                unsigned long long d2 = pack2(xa0.z, xa0.z), d3 = pack2(xa0.w, xa0.w);
                unsigned long long d4 = pack2(xb0.x, xb0.x), d5 = pack2(xb0.y, xb0.y);
                unsigned long long d6 = pack2(xb0.z, xb0.z), d7 = pack2(xb0.w, xb0.w);
                acc[0][0] = ffma2(q0.x, d0, acc[0][0]); acc[0][1] = ffma2(q0.x, d1, acc[0][1]);
                acc[0][2] = ffma2(q0.x, d2, acc[0][2]); acc[0][3] = ffma2(q0.x, d3, acc[0][3]);
                acc[0][4] = ffma2(q0.x, d4, acc[0][4]); acc[0][5] = ffma2(q0.x, d5, acc[0][5]);
                acc[0][6] = ffma2(q0.x, d6, acc[0][6]); acc[0][7] = ffma2(q0.x, d7, acc[0][7]);
                acc[1][0] = ffma2(q1.x, d0, acc[1][0]); acc[1][1] = ffma2(q1.x, d1, acc[1][1]);
                acc[1][2] = ffma2(q1.x, d2, acc[1][2]); acc[1][3] = ffma2(q1.x, d3, acc[1][3]);
                acc[1][4] = ffma2(q1.x, d4, acc[1][4]); acc[1][5] = ffma2(q1.x, d5, acc[1][5]);
                acc[1][6] = ffma2(q1.x, d6, acc[1][6]); acc[1][7] = ffma2(q1.x, d7, acc[1][7]);
                acc[2][0] = ffma2(q2.x, d0, acc[2][0]); acc[2][1] = ffma2(q2.x, d1, acc[2][1]);
                acc[2][2] = ffma2(q2.x, d2, acc[2][2]); acc[2][3] = ffma2(q2.x, d3, acc[2][3]);
                acc[2][4] = ffma2(q2.x, d4, acc[2][4]); acc[2][5] = ffma2(q2.x, d5, acc[2][5]);
                acc[2][6] = ffma2(q2.x, d6, acc[2][6]); acc[2][7] = ffma2(q2.x, d7, acc[2][7]);
                acc[3][0] = ffma2(q3.x, d0, acc[3][0]); acc[3][1] = ffma2(q3.x, d1, acc[3][1]);
                acc[3][2] = ffma2(q3.x, d2, acc[3][2]); acc[3][3] = ffma2(q3.x, d3, acc[3][3]);
                acc[3][4] = ffma2(q3.x, d4, acc[3][4]); acc[3][5] = ffma2(q3.x, d5, acc[3][5]);
                acc[3][6] = ffma2(q3.x, d6, acc[3][6]); acc[3][7] = ffma2(q3.x, d7, acc[3][7]);
            }
            {   // j = j2 + 1
                unsigned long long d0 = pack2(xa1.x, xa1.x), d1 = pack2(xa1.y, xa1.y);
                unsigned long long d2 = pack2(xa1.z, xa1.z), d3 = pack2(xa1.w, xa1.w);
                unsigned long long d4 = pack2(xb1.x, xb1.x), d5 = pack2(xb1.y, xb1.y);
                unsigned long long d6 = pack2(xb1.z, xb1.z), d7 = pack2(xb1.w, xb1.w);
                acc[0][0] = ffma2(q0.y, d0, acc[0][0]); acc[0][1] = ffma2(q0.y, d1, acc[0][1]);
                acc[0][2] = ffma2(q0.y, d2, acc[0][2]); acc[0][3] = ffma2(q0.y, d3, acc[0][3]);
                acc[0][4] = ffma2(q0.y, d4, acc[0][4]); acc[0][5] = ffma2(q0.y, d5, acc[0][5]);
                acc[0][6] = ffma2(q0.y, d6, acc[0][6]); acc[0][7] = ffma2(q0.y, d7, acc[0][7]);
                acc[1][0] = ffma2(q1.y, d0, acc[1][0]); acc[1][1] = ffma2(q1.y, d1, acc[1][1]);
                acc[1][2] = ffma2(q1.y, d2, acc[1][2]); acc[1][3] = ffma2(q1.y, d3, acc[1][3]);
                acc[1][4] = ffma2(q1.y, d4, acc[1][4]); acc[1][5] = ffma2(q1.y, d5, acc[1][5]);
                acc[1][6] = ffma2(q1.y, d6, acc[1][6]); acc[1][7] = ffma2(q1.y, d7, acc[1][7]);
                acc[2][0] = ffma2(q2.y, d0, acc[2][0]); acc[2][1] = ffma2(q2.y, d1, acc[2][1]);
                acc[2][2] = ffma2(q2.y, d2, acc[2][2]); acc[2][3] = ffma2(q2.y, d3, acc[2][3]);
                acc[2][4] = ffma2(q2.y, d4, acc[2][4]); acc[2][5] = ffma2(q2.y, d5, acc[2][5]);
                acc[2][6] = ffma2(q2.y, d6, acc[2][6]); acc[2][7] = ffma2(q2.y, d7, acc[2][7]);
                acc[3][0] = ffma2(q3.y, d0, acc[3][0]); acc[3][1] = ffma2(q3.y, d1, acc[3][1]);
                acc[3][2] = ffma2(q3.y, d2, acc[3][2]); acc[3][3] = ffma2(q3.y, d3, acc[3][3]);
                acc[3][4] = ffma2(q3.y, d4, acc[3][4]); acc[3][5] = ffma2(q3.y, d5, acc[3][5]);
                acc[3][6] = ffma2(q3.y, d6, acc[3][6]); acc[3][7] = ffma2(q3.y, d7, acc[3][7]);
            }
        }
        __syncthreads();   // all reads of this buffer done before it is refilled
    }

    // epilogue: out[b][c][w*1024 + t]
    int b = bw >> 4, w = bw & 15;
    float* op = out + (size_t)b * 1048576 + (size_t)w * 1024 + tbase;
#pragma unroll
    for (int c2 = 0; c2 < 4; c2++) {
        int ch0 = warp * 8 + 2 * c2;
        float f0[8], f1[8];
#pragma unroll
        for (int t = 0; t < 8; t++) unpack2(acc[c2][t], f0[t], f1[t]);
        float4* p0 = reinterpret_cast<float4*>(op + (size_t)ch0 * 16384);
        float4* p1 = reinterpret_cast<float4*>(op + (size_t)(ch0 + 1) * 16384);
        p0[0] = make_float4(f0[0], f0[1], f0[2], f0[3]);
        p0[1] = make_float4(f0[4], f0[5], f0[6], f0[7]);
        p1[0] = make_float4(f1[0], f1[1], f1[2], f1[3]);
        p1[1] = make_float4(f1[4], f1[5], f1[6], f1[7]);
    }
}

// ================= launch =================
extern "C" void kernel_launch(void* const* d_in, const int* in_sizes, int n_in,
                              void* d_out, int out_size) {
    const float* x     = (const float*)d_in[0];
    const float* Wp    = (const float*)d_in[1];
    const float* w1    = (const float*)d_in[2];
    const float* b1    = (const float*)d_in[3];
    const float* w2    = (const float*)d_in[4];
    const float* b2    = (const float*)d_in[5];
    const float* beta  = (const float*)d_in[6];
    const float* gamma = (const float*)d_in[7];
    const float* temp  = (const float*)d_in[8];
    float* out = (float*)d_out;

    k_stats<<<8192, 256>>>(x);
    k_zmean<<<64, 256>>>(Wp);
    k_graph<<<1, GNT>>>(w1, b1, w2, b2, beta, gamma, temp, out + XR_ELEMS);
    k_prop<<<4096, 256>>>(x, out);
}